// round 15
// baseline (speedup 1.0000x reference)
#include <cuda_runtime.h>
#include <math.h>
#include <stdint.h>

#define BATCH 2
#define SEQ   2048
#define DM    1024
#define NH    16
#define DK    64
#define DFF   4096
#define MTOT  (BATCH*SEQ)   // 4096 rows

#if defined(__CUDA_ARCH__) && defined(__CUDA_ARCH_FEAT_SM103_ALL)
#define HAS_TCGEN05 1
#else
#define HAS_TCGEN05 0
#endif

// ---------------- scratch (device globals; no allocations allowed) ----------
__device__ float g_q  [MTOT*DM];
__device__ float g_k  [MTOT*DM];
__device__ float g_vt [MTOT*DM];      // V transposed per (b,h): [bh][64 d][2048 j]
__device__ float g_ctx[MTOT*DM];
__device__ float g_att [MTOT*DM];     // Wo partial (K-half 0, + bias)
__device__ float g_att2[MTOT*DM];     // Wo partial (K-half 1)
__device__ float g_h  [MTOT*DM];
__device__ float g_ff1[(size_t)MTOT*DFF];
__device__ float g_ff2 [MTOT*DM];     // FF2 partial (K-half 0, + bias)
__device__ float g_ff2b[MTOT*DM];     // FF2 partial (K-half 1)
// transposed (K-major) weights (stored pre-rounded to tf32)
__device__ float g_Wqkv[3*DM*DM];     // [Wq^T | Wk^T | Wv^T] rows
__device__ float g_Wot[DM*DM];
__device__ float g_W1t[(size_t)DM*DFF];
__device__ float g_W2t[(size_t)DM*DFF];

// ======================= PTX helpers =========================================
__device__ __forceinline__ uint32_t smem_u32(const void* p) {
    uint32_t a;
    asm("{ .reg .u64 t; cvta.to.shared.u64 t, %1; cvt.u32.u64 %0, t; }" : "=r"(a) : "l"(p));
    return a;
}
__device__ __forceinline__ uint32_t f2tf32(float f) {
    uint32_t r;
    asm("cvt.rna.tf32.f32 %0, %1;" : "=r"(r) : "f"(f));
    return r;
}
__device__ __forceinline__ void mbar_init(uint32_t mbar, uint32_t cnt) {
    asm volatile("mbarrier.init.shared.b64 [%0], %1;" :: "r"(mbar), "r"(cnt) : "memory");
}
__device__ __forceinline__ void mbar_wait(uint32_t mbar, uint32_t parity) {
    asm volatile(
        "{\n\t.reg .pred P;\n"
        "WL_%=:\n\t"
        "mbarrier.try_wait.parity.shared.b64 P, [%0], %1;\n\t"
        "@!P bra WL_%=;\n\t}"
        :: "r"(mbar), "r"(parity) : "memory");
}
// 16-byte async copy gmem -> (pre-swizzled) smem address
__device__ __forceinline__ void cp16(uint32_t dst, const void* src) {
    asm volatile("cp.async.cg.shared.global [%0], [%1], 16;"
                 :: "r"(dst), "l"(src) : "memory");
}
__device__ __forceinline__ void cp_commit() {
    asm volatile("cp.async.commit_group;" ::: "memory");
}
__device__ __forceinline__ void cp_wait0() {
    asm volatile("cp.async.wait_group 0;" ::: "memory");
}
__device__ __forceinline__ void cp_wait1() {
    asm volatile("cp.async.wait_group 1;" ::: "memory");
}
// SW128 K-major smem descriptor (layout=2, version=1, SBO=64, LBO=1)
#define DESC_BASE_SW128 ((2ull<<61)|(1ull<<46)|(64ull<<32)|(1ull<<16))
__device__ __forceinline__ uint64_t make_desc(uint32_t addr) {
    return DESC_BASE_SW128 | ((uint64_t)(addr >> 4) & 0x3FFF);
}
#define SW128(off) ((off) ^ (((off) >> 3) & 0x70))

// tf32 idesc: dtype F32=1<<4, atype TF32=2<<7, btype TF32=2<<10, N/8<<17, M/16<<24
#define IDESC_TF32(M_, N_) ((1u<<4)|(2u<<7)|(2u<<10)|(((N_)/8u)<<17)|(((M_)/16u)<<24))

#if HAS_TCGEN05
__device__ __forceinline__ void mma_tf32_ss(uint32_t d_tmem, uint64_t a_desc,
                                            uint64_t b_desc, uint32_t idesc, uint32_t en) {
    asm volatile(
        "{\n\t.reg .pred p;\n\t"
        "setp.ne.u32 p, %4, 0;\n\t"
        "tcgen05.mma.cta_group::1.kind::tf32 [%0], %1, %2, %3, {%5,%5,%5,%5}, p;\n\t}"
        :: "r"(d_tmem), "l"(a_desc), "l"(b_desc), "r"(idesc), "r"(en), "r"(0u)
        : "memory");
}
// TS form: A from TMEM
__device__ __forceinline__ void mma_tf32_ts(uint32_t d_tmem, uint32_t a_tmem,
                                            uint64_t b_desc, uint32_t idesc, uint32_t en) {
    asm volatile(
        "{\n\t.reg .pred p;\n\t"
        "setp.ne.u32 p, %4, 0;\n\t"
        "tcgen05.mma.cta_group::1.kind::tf32 [%0], [%1], %2, %3, {%5,%5,%5,%5}, p;\n\t}"
        :: "r"(d_tmem), "r"(a_tmem), "l"(b_desc), "r"(idesc), "r"(en), "r"(0u)
        : "memory");
}
__device__ __forceinline__ void tmem_ld32(uint32_t* r, uint32_t addr) {
    asm volatile(
        "tcgen05.ld.sync.aligned.32x32b.x32.b32 "
        "{%0,%1,%2,%3,%4,%5,%6,%7,%8,%9,%10,%11,%12,%13,%14,%15,"
        "%16,%17,%18,%19,%20,%21,%22,%23,%24,%25,%26,%27,%28,%29,%30,%31}, [%32];"
        : "=r"(r[0]),"=r"(r[1]),"=r"(r[2]),"=r"(r[3]),"=r"(r[4]),"=r"(r[5]),
          "=r"(r[6]),"=r"(r[7]),"=r"(r[8]),"=r"(r[9]),"=r"(r[10]),"=r"(r[11]),
          "=r"(r[12]),"=r"(r[13]),"=r"(r[14]),"=r"(r[15]),"=r"(r[16]),"=r"(r[17]),
          "=r"(r[18]),"=r"(r[19]),"=r"(r[20]),"=r"(r[21]),"=r"(r[22]),"=r"(r[23]),
          "=r"(r[24]),"=r"(r[25]),"=r"(r[26]),"=r"(r[27]),"=r"(r[28]),"=r"(r[29]),
          "=r"(r[30]),"=r"(r[31])
        : "r"(addr));
}
__device__ __forceinline__ void tmem_st32(uint32_t addr, const uint32_t* r) {
    asm volatile(
        "tcgen05.st.sync.aligned.32x32b.x32.b32 [%0], "
        "{%1,%2,%3,%4,%5,%6,%7,%8,%9,%10,%11,%12,%13,%14,%15,%16,"
        "%17,%18,%19,%20,%21,%22,%23,%24,%25,%26,%27,%28,%29,%30,%31,%32};"
        :: "r"(addr),
           "r"(r[0]),"r"(r[1]),"r"(r[2]),"r"(r[3]),"r"(r[4]),"r"(r[5]),
           "r"(r[6]),"r"(r[7]),"r"(r[8]),"r"(r[9]),"r"(r[10]),"r"(r[11]),
           "r"(r[12]),"r"(r[13]),"r"(r[14]),"r"(r[15]),"r"(r[16]),"r"(r[17]),
           "r"(r[18]),"r"(r[19]),"r"(r[20]),"r"(r[21]),"r"(r[22]),"r"(r[23]),
           "r"(r[24]),"r"(r[25]),"r"(r[26]),"r"(r[27]),"r"(r[28]),"r"(r[29]),
           "r"(r[30]),"r"(r[31])
        : "memory");
}
#endif

// ======================= tcgen05 tf32 GEMM (R12 + split-K via gridDim.z) =====
// C = A[M,*,lda] @ Bt[N,*,lda]^T over K columns starting at blockIdx.z*K.
// mode 0: plain -> (z==0 ? out0 : out1); bias b0 added only by z==0.
// mode 1: +GELU -> out0/b0 (z must be 0). mode 2: fused QKV (z must be 0).
// Tile 128x128, K-chunk 32, 2-stage 2x32KB dynamic smem -> 3 CTAs/SM.
#define GSM_BUF   32768              // A @ +0 (16KB), B @ +16KB per buffer
#define GSM_BOFF  16384
#define GSM_CTRL  (2*GSM_BUF)        // 64KB
#define GSM_SIZE  (GSM_CTRL + 1024)

#if HAS_TCGEN05
__device__ __forceinline__ void gemm_load_chunk_async(
    const float* __restrict__ A, const float* __restrict__ Bt, int lda,
    int rowBase, int colBase, int k0, uint32_t buf, int tid)
{
#pragma unroll
    for (int t = 0; t < 4; ++t) {
        int i   = tid + t * 256;
        int row = i >> 3;
        int qq  = i & 7;
        cp16(buf + SW128((uint32_t)(row * 128 + qq * 16)),
             A + (size_t)(rowBase + row) * lda + k0 + qq * 4);
    }
#pragma unroll
    for (int t = 0; t < 4; ++t) {
        int i   = tid + t * 256;
        int row = i >> 3;
        int qq  = i & 7;
        cp16(buf + GSM_BOFF + SW128((uint32_t)(row * 128 + qq * 16)),
             Bt + (size_t)(colBase + row) * lda + k0 + qq * 4);
    }
    cp_commit();
}
#endif

__global__ __launch_bounds__(256) void tc_gemm_kernel(
    const float* __restrict__ A, const float* __restrict__ Bt,
    const float* __restrict__ b0, const float* __restrict__ b1,
    const float* __restrict__ b2,
    float* __restrict__ out0, float* __restrict__ out1, float* __restrict__ vt,
    int M, int N, int K, int lda, int mode)
{
#if HAS_TCGEN05
    extern __shared__ __align__(1024) char smem[];
    const uint32_t sbase = smem_u32(smem);
    const uint32_t mb0   = sbase + GSM_CTRL + 8;
    const uint32_t mb1   = sbase + GSM_CTRL + 16;
    const int tid = threadIdx.x;
    const int wid = tid >> 5;
    const int lid = tid & 31;

    const int rowBase = blockIdx.y * 128;
    const int colBase = blockIdx.x * 128;
    const int kBase   = blockIdx.z * K;       // split-K offset

    if (wid == 0) {
        asm volatile("tcgen05.alloc.cta_group::1.sync.aligned.shared::cta.b32 [%0], %1;"
                     :: "r"(sbase + GSM_CTRL), "r"(128u) : "memory");
        asm volatile("tcgen05.relinquish_alloc_permit.cta_group::1.sync.aligned;");
    }
    if (tid == 0) { mbar_init(mb0, 1); mbar_init(mb1, 1); }
    __syncthreads();
    uint32_t tmem_base;
    asm volatile("ld.shared.b32 %0, [%1];" : "=r"(tmem_base) : "r"(sbase + GSM_CTRL));

    const int nchunks = K >> 5;
    uint32_t pend0 = 0, pend1 = 0;

    gemm_load_chunk_async(A, Bt, lda, rowBase, colBase, kBase, sbase, tid);

    for (int c = 0; c < nchunks; ++c) {
        const int b = c & 1;

        if (c + 1 < nchunks) {
            if (b ^ 1) { if (pend1) mbar_wait(mb1, (pend1 - 1) & 1); }
            else       { if (pend0) mbar_wait(mb0, (pend0 - 1) & 1); }
            gemm_load_chunk_async(A, Bt, lda, rowBase, colBase, kBase + ((c + 1) << 5),
                                  sbase + (uint32_t)(b ^ 1) * GSM_BUF, tid);
            cp_wait1();
        } else {
            cp_wait0();
        }
        asm volatile("fence.proxy.async.shared::cta;" ::: "memory");
        __syncthreads();

        if (tid == 0) {
            const uint32_t buf = sbase + (uint32_t)b * GSM_BUF;
            uint64_t ad = make_desc(buf);
            uint64_t bd = make_desc(buf + GSM_BOFF);
#pragma unroll
            for (int s = 0; s < 4; ++s)
                mma_tf32_ss(tmem_base, ad + s * 2, bd + s * 2, IDESC_TF32(128,128),
                            (c > 0 || s > 0) ? 1u : 0u);
            asm volatile(
                "tcgen05.commit.cta_group::1.mbarrier::arrive::one.shared::cluster.b64 [%0];"
                :: "r"(b ? mb1 : mb0) : "memory");
        }
        if (b) ++pend1; else ++pend0;
    }

    if (pend0) mbar_wait(mb0, (pend0 - 1) & 1);
    if (pend1) mbar_wait(mb1, (pend1 - 1) & 1);
    asm volatile("tcgen05.fence::after_thread_sync;" ::: "memory");

    // ---- epilogue ----
    {
        const int sub  = wid & 3;
        const int half = wid >> 2;
        const int row  = rowBase + sub * 32 + lid;
        const int z    = blockIdx.z;
#pragma unroll
        for (int g = 0; g < 2; ++g) {
            const int colOff = half * 64 + g * 32;
            uint32_t r[32];
            tmem_ld32(r, tmem_base + colOff);
            asm volatile("tcgen05.wait::ld.sync.aligned;" ::: "memory");

            if (mode == 2) {
                const int cglob = colBase + colOff;
                const int which = cglob >> 10;
                const int cloc  = cglob & 1023;
                if (which < 2) {
                    float* out = which ? out1 : out0;
                    const float* bias = which ? b1 : b0;
                    float* crow = out + (size_t)row * DM + cloc;
#pragma unroll
                    for (int j4 = 0; j4 < 8; ++j4) {
                        float4 o;
                        o.x = __uint_as_float(r[j4*4+0]) + bias[cloc + j4*4+0];
                        o.y = __uint_as_float(r[j4*4+1]) + bias[cloc + j4*4+1];
                        o.z = __uint_as_float(r[j4*4+2]) + bias[cloc + j4*4+2];
                        o.w = __uint_as_float(r[j4*4+3]) + bias[cloc + j4*4+3];
                        *(float4*)(crow + j4 * 4) = o;
                    }
                } else {
                    const int bb = row >> 11;
                    const int j  = row & 2047;
                    float* base = vt + ((size_t)(bb * NH + (cloc >> 6)) * DK
                                        + (cloc & 63)) * SEQ + j;
#pragma unroll
                    for (int cc = 0; cc < 32; ++cc)
                        base[(size_t)cc * SEQ] = __uint_as_float(r[cc]) + b2[cloc + cc];
                }
            } else {
                float* out = z ? out1 : out0;
                float* crow = out + (size_t)row * N + colBase + colOff;
#pragma unroll
                for (int j4 = 0; j4 < 8; ++j4) {
                    float4 o;
                    float bv0 = z ? 0.f : b0[colBase + colOff + j4*4+0];
                    float bv1 = z ? 0.f : b0[colBase + colOff + j4*4+1];
                    float bv2 = z ? 0.f : b0[colBase + colOff + j4*4+2];
                    float bv3 = z ? 0.f : b0[colBase + colOff + j4*4+3];
                    float v0 = __uint_as_float(r[j4*4+0]) + bv0;
                    float v1 = __uint_as_float(r[j4*4+1]) + bv1;
                    float v2 = __uint_as_float(r[j4*4+2]) + bv2;
                    float v3 = __uint_as_float(r[j4*4+3]) + bv3;
                    if (mode == 1) {
                        v0 = 0.5f * v0 * (1.f + erff(v0 * 0.70710678118654752440f));
                        v1 = 0.5f * v1 * (1.f + erff(v1 * 0.70710678118654752440f));
                        v2 = 0.5f * v2 * (1.f + erff(v2 * 0.70710678118654752440f));
                        v3 = 0.5f * v3 * (1.f + erff(v3 * 0.70710678118654752440f));
                    }
                    o.x = v0; o.y = v1; o.z = v2; o.w = v3;
                    *(float4*)(crow + j4 * 4) = o;
                }
            }
        }
    }
    asm volatile("tcgen05.fence::before_thread_sync;" ::: "memory");
    __syncthreads();
    if (wid == 0) {
        asm volatile("tcgen05.dealloc.cta_group::1.sync.aligned.b32 %0, %1;"
                     :: "r"(tmem_base), "r"(128u));
    }
#endif
}

// ======================= tcgen05 tf32 flash attention (R8 proven) ============
#define ASM_Q    0
#define ASM_K    32768
#define ASM_VT   65536
#define ASM_CTRL 98304
#define ASM_SIZE (98304 + 1024)

__global__ __launch_bounds__(256, 2) void tc_attention_kernel(
    const float* __restrict__ q, const float* __restrict__ k,
    const float* __restrict__ vt, float* __restrict__ ctx)
{
#if HAS_TCGEN05
    extern __shared__ __align__(1024) char smem[];
    const uint32_t sbase = smem_u32(smem);
    const uint32_t mbar  = sbase + ASM_CTRL + 8;
    const int tid = threadIdx.x;
    const int wid = tid >> 5;
    const int lid = tid & 31;

    const int bh = blockIdx.y;
    const int b  = bh / NH;
    const int h  = bh % NH;
    const int q0 = blockIdx.x * 128;

    const float* qb  = q  + (size_t)(b * SEQ + q0) * DM + h * DK;
    const float* kb  = k  + (size_t)b * SEQ * DM + h * DK;
    const float* vtb = vt + (size_t)bh * DK * SEQ;

    if (wid == 0) {
        asm volatile("tcgen05.alloc.cta_group::1.sync.aligned.shared::cta.b32 [%0], %1;"
                     :: "r"(sbase + ASM_CTRL), "r"(256u) : "memory");
        asm volatile("tcgen05.relinquish_alloc_permit.cta_group::1.sync.aligned;");
    }
    if (tid == 0) mbar_init(mbar, 1);
    __syncthreads();
    uint32_t tmem_base;
    asm volatile("ld.shared.b32 %0, [%1];" : "=r"(tmem_base) : "r"(sbase + ASM_CTRL));
    const uint32_t tS = tmem_base;
    const uint32_t tO = tmem_base + 128;

#pragma unroll
    for (int t = 0; t < 8; ++t) {
        int i   = tid + t * 256;
        int row = i >> 4;
        int d0  = (i & 15) * 4;
        cp16(sbase + ASM_Q + ((uint32_t)(d0 >> 5)) * 16384u
             + SW128((uint32_t)(row * 128 + (d0 & 31) * 4)),
             qb + (size_t)row * DM + d0);
    }
    cp_commit();

    const int sub  = wid & 3;
    const int half = wid >> 2;
    const int r    = sub * 32 + lid;
    const uint32_t st_off = ((uint32_t)sub) << 21;

    float lsum = 0.f;
    uint32_t cnt = 0;

    const uint64_t dQ  = make_desc(sbase + ASM_Q);
    const uint64_t dK  = make_desc(sbase + ASM_K);
    const uint64_t dVt = make_desc(sbase + ASM_VT);

    for (int j0 = 0; j0 < SEQ; j0 += 128) {
#pragma unroll
        for (int t = 0; t < 8; ++t) {
            int i   = tid + t * 256;
            int row = i >> 4;
            int d0  = (i & 15) * 4;
            cp16(sbase + ASM_K + ((uint32_t)(d0 >> 5)) * 16384u
                 + SW128((uint32_t)(row * 128 + (d0 & 31) * 4)),
                 kb + (size_t)(j0 + row) * DM + d0);
        }
#pragma unroll
        for (int t = 0; t < 8; ++t) {
            int i    = tid + t * 256;
            int rowd = i >> 5;
            int jj   = (i & 31) * 4;
            cp16(sbase + ASM_VT + ((uint32_t)(jj >> 5)) * 8192u
                 + SW128((uint32_t)(rowd * 128 + (jj & 31) * 4)),
                 vtb + (size_t)rowd * SEQ + j0 + jj);
        }
        cp_commit();
        cp_wait0();
        asm volatile("fence.proxy.async.shared::cta;" ::: "memory");
        __syncthreads();

        if (tid == 0) {
#pragma unroll
            for (int s = 0; s < 8; ++s) {
                uint64_t off = (uint64_t)((s >> 2) * 1024 + (s & 3) * 2);
                mma_tf32_ss(tS, dQ + off, dK + off, IDESC_TF32(128,128), s > 0 ? 1u : 0u);
            }
            asm volatile(
                "tcgen05.commit.cta_group::1.mbarrier::arrive::one.shared::cluster.b64 [%0];"
                :: "r"(mbar) : "memory");
        }
        mbar_wait(mbar, cnt & 1); ++cnt;
        asm volatile("tcgen05.fence::after_thread_sync;" ::: "memory");

#pragma unroll
        for (int g = 0; g < 2; ++g) {
            const int c0 = half * 64 + g * 32;
            uint32_t sreg[32];
            tmem_ld32(sreg, tS + c0);
            asm volatile("tcgen05.wait::ld.sync.aligned;" ::: "memory");
#pragma unroll
            for (int j = 0; j < 32; ++j) {
                float p = __expf(__uint_as_float(sreg[j]) * 0.125f);
                lsum += p;
                sreg[j] = f2tf32(p);
            }
            tmem_st32(tS + c0 + st_off, sreg);
        }
        asm volatile("tcgen05.wait::st.sync.aligned;" ::: "memory");
        asm volatile("tcgen05.fence::before_thread_sync;" ::: "memory");
        __syncthreads();

        if (tid == 0) {
            asm volatile("tcgen05.fence::after_thread_sync;" ::: "memory");
#pragma unroll
            for (int s = 0; s < 16; ++s) {
                uint64_t offB = (uint64_t)((s >> 2) * 512 + (s & 3) * 2);
                mma_tf32_ts(tO, tS + s * 8, dVt + offB, IDESC_TF32(128,64),
                            (j0 > 0 || s > 0) ? 1u : 0u);
            }
            asm volatile(
                "tcgen05.commit.cta_group::1.mbarrier::arrive::one.shared::cluster.b64 [%0];"
                :: "r"(mbar) : "memory");
        }
        mbar_wait(mbar, cnt & 1); ++cnt;
        __syncthreads();
    }

    asm volatile("tcgen05.fence::after_thread_sync;" ::: "memory");

    {
        float* l_arr = (float*)(smem + ASM_K);
        l_arr[half * 128 + r] = lsum;
    }
    __syncthreads();
    float ltot;
    {
        float* l_arr = (float*)(smem + ASM_K);
        ltot = l_arr[r] + l_arr[128 + r];
    }
    const float inv = 1.f / ltot;

    {
        const int c0 = half * 32;
        uint32_t oreg[32];
        tmem_ld32(oreg, tO + c0);
        asm volatile("tcgen05.wait::ld.sync.aligned;" ::: "memory");
        float* orow = ctx + (size_t)(b * SEQ + q0 + r) * DM + h * DK + c0;
#pragma unroll
        for (int j4 = 0; j4 < 8; ++j4) {
            float4 o;
            o.x = __uint_as_float(oreg[j4*4+0]) * inv;
            o.y = __uint_as_float(oreg[j4*4+1]) * inv;
            o.z = __uint_as_float(oreg[j4*4+2]) * inv;
            o.w = __uint_as_float(oreg[j4*4+3]) * inv;
            *(float4*)(orow + j4 * 4) = o;
        }
    }
    asm volatile("tcgen05.fence::before_thread_sync;" ::: "memory");
    __syncthreads();
    if (wid == 0) {
        asm volatile("tcgen05.dealloc.cta_group::1.sync.aligned.b32 %0, %1;"
                     :: "r"(tmem_base), "r"(256u));
    }
#endif
}

// ======================= fused weight transpose (ALL 6 in one launch) ========
__global__ __launch_bounds__(256) void transpose_all_kernel(
    const float* __restrict__ Wq, const float* __restrict__ Wk,
    const float* __restrict__ Wv, const float* __restrict__ Wo,
    const float* __restrict__ W1, const float* __restrict__ W2,
    float* __restrict__ Wqkv, float* __restrict__ Wot,
    float* __restrict__ W1t,  float* __restrict__ W2t)
{
    __shared__ float t[32][33];
    const int bid = blockIdx.x;
    const float* in; float* out; int R, C, idx;

    if (bid < 4096) {
        R = DM; C = DM; idx = bid & 1023;
        const int j = bid >> 10;
        in  = (j == 0) ? Wq : (j == 1) ? Wk : (j == 2) ? Wv : Wo;
        out = (j == 3) ? Wot : Wqkv + (size_t)j * DM * DM;
    } else if (bid < 8192) {
        R = DM; C = DFF; idx = bid - 4096;
        in = W1; out = W1t;
    } else {
        R = DFF; C = DM; idx = bid - 8192;
        in = W2; out = W2t;
    }
    const int Ct = C >> 5;
    const int c0 = (idx % Ct) * 32;
    const int r0 = (idx / Ct) * 32;
    const int x = threadIdx.x & 31;
    const int y = threadIdx.x >> 5;
#pragma unroll
    for (int i = y; i < 32; i += 8)
        t[i][x] = in[(size_t)(r0 + i) * C + c0 + x];
    __syncthreads();
#pragma unroll
    for (int i = y; i < 32; i += 8)
        out[(size_t)(c0 + i) * R + r0 + x] = __uint_as_float(f2tf32(t[x][i]));
}

// ======================= fused residual + LayerNorm (3-input) ================
// out = LN(X + Y0 + Y1) * g + be
__global__ __launch_bounds__(256) void ln_residual3_kernel(
    const float* __restrict__ X, const float* __restrict__ Y0,
    const float* __restrict__ Y1,
    const float* __restrict__ g, const float* __restrict__ be,
    float* __restrict__ out)
{
    __shared__ float buf[DM];
    __shared__ float red1[256], red2[256];

    const int row = blockIdx.x;
    const int tid = threadIdx.x;
    const size_t base = (size_t)row * DM;

    float s = 0.f, s2 = 0.f;
#pragma unroll
    for (int c = tid; c < DM; c += 256) {
        float vv = X[base + c] + Y0[base + c] + Y1[base + c];
        buf[c] = vv;
        s  += vv;
        s2 += vv * vv;
    }
    red1[tid] = s; red2[tid] = s2;
    __syncthreads();
    for (int off = 128; off > 0; off >>= 1) {
        if (tid < off) {
            red1[tid] += red1[tid + off];
            red2[tid] += red2[tid + off];
        }
        __syncthreads();
    }
    const float mu  = red1[0] * (1.f / DM);
    const float var = red2[0] * (1.f / DM) - mu * mu;
    const float rs  = rsqrtf(var + 1e-5f);

#pragma unroll
    for (int c = tid; c < DM; c += 256)
        out[base + c] = (buf[c] - mu) * rs * g[c] + be[c];
}

// ======================= launch ==============================================
extern "C" void kernel_launch(void* const* d_in, const int* in_sizes, int n_in,
                              void* d_out, int out_size)
{
    const float* x  = (const float*)d_in[0];
    const float* Wq = (const float*)d_in[1];  const float* bq = (const float*)d_in[2];
    const float* Wk = (const float*)d_in[3];  const float* bk = (const float*)d_in[4];
    const float* Wv = (const float*)d_in[5];  const float* bv = (const float*)d_in[6];
    const float* Wo = (const float*)d_in[7];  const float* bo = (const float*)d_in[8];
    const float* W1 = (const float*)d_in[9];  const float* b1 = (const float*)d_in[10];
    const float* W2 = (const float*)d_in[11]; const float* b2 = (const float*)d_in[12];
    const float* g1 = (const float*)d_in[13]; const float* be1 = (const float*)d_in[14];
    const float* g2 = (const float*)d_in[15]; const float* be2 = (const float*)d_in[16];

    float *q, *k, *vt, *ctx, *att, *att2, *h, *ff1, *ff2, *ff2b;
    float *Wqkv, *Wot, *W1t, *W2t;
    cudaGetSymbolAddress((void**)&q,    g_q);
    cudaGetSymbolAddress((void**)&k,    g_k);
    cudaGetSymbolAddress((void**)&vt,   g_vt);
    cudaGetSymbolAddress((void**)&ctx,  g_ctx);
    cudaGetSymbolAddress((void**)&att,  g_att);
    cudaGetSymbolAddress((void**)&att2, g_att2);
    cudaGetSymbolAddress((void**)&h,    g_h);
    cudaGetSymbolAddress((void**)&ff1,  g_ff1);
    cudaGetSymbolAddress((void**)&ff2,  g_ff2);
    cudaGetSymbolAddress((void**)&ff2b, g_ff2b);
    cudaGetSymbolAddress((void**)&Wqkv, g_Wqkv);
    cudaGetSymbolAddress((void**)&Wot,  g_Wot);
    cudaGetSymbolAddress((void**)&W1t,  g_W1t);
    cudaGetSymbolAddress((void**)&W2t,  g_W2t);

    static int smem_set = 0;
    if (!smem_set) {
        cudaFuncSetAttribute(tc_attention_kernel,
                             cudaFuncAttributeMaxDynamicSharedMemorySize, ASM_SIZE);
        cudaFuncSetAttribute(tc_gemm_kernel,
                             cudaFuncAttributeMaxDynamicSharedMemorySize, GSM_SIZE);
        smem_set = 1;
    }

    // ---- all 6 weight transposes (tf32-rounded) in ONE launch ----
    transpose_all_kernel<<<12288, 256>>>(Wq, Wk, Wv, Wo, W1, W2,
                                         Wqkv, Wot, W1t, W2t);

    const dim3 gQKV (3*DM / 128, MTOT / 128, 1);   // (24, 32, 1)
    const dim3 gProjS(DM / 128,  MTOT / 128, 2);   // (8, 32, 2) split-K
    const dim3 gFF1 (DFF / 128,  MTOT / 128, 1);   // (32, 32, 1)

    // fused QKV projection (V written transposed)
    tc_gemm_kernel<<<gQKV, 256, GSM_SIZE>>>(x, Wqkv, bq, bk, bv, q, k, vt,
                                            MTOT, 3*DM, DM, DM, 2);

    // attention (tf32 tensor cores, P in TMEM)
    tc_attention_kernel<<<dim3(SEQ / 128, BATCH * NH), 256, ASM_SIZE>>>(q, k, vt, ctx);

    // output projection: split-K=2 -> att (z0, +bias) / att2 (z1)
    tc_gemm_kernel<<<gProjS, 256, GSM_SIZE>>>(ctx, Wot, bo, 0, 0, att, att2, 0,
                                              MTOT, DM, DM/2, DM, 0);

    // residual + LN1 (3-input) -> h
    ln_residual3_kernel<<<MTOT, 256>>>(x, att, att2, g1, be1, h);

    // FFN
    tc_gemm_kernel<<<gFF1, 256, GSM_SIZE>>>(h, W1t, b1, 0, 0, ff1, 0, 0,
                                            MTOT, DFF, DM, DM, 1);
    // FF2: split-K=2 -> ff2 (z0, +bias) / ff2b (z1)
    tc_gemm_kernel<<<gProjS, 256, GSM_SIZE>>>(ff1, W2t, b2, 0, 0, ff2, ff2b, 0,
                                              MTOT, DM, DFF/2, DFF, 0);

    // residual + LN2 (3-input) -> output
    ln_residual3_kernel<<<MTOT, 256>>>(h, ff2, ff2b, g2, be2, (float*)d_out);
}

// round 16
// speedup vs baseline: 1.0680x; 1.0680x over previous
#include <cuda_runtime.h>
#include <math.h>
#include <stdint.h>

#define BATCH 2
#define SEQ   2048
#define DM    1024
#define NH    16
#define DK    64
#define DFF   4096
#define MTOT  (BATCH*SEQ)   // 4096 rows

#if defined(__CUDA_ARCH__) && defined(__CUDA_ARCH_FEAT_SM103_ALL)
#define HAS_TCGEN05 1
#else
#define HAS_TCGEN05 0
#endif

// ---------------- scratch (device globals; no allocations allowed) ----------
__device__ float g_q  [MTOT*DM];
__device__ float g_k  [MTOT*DM];
__device__ float g_vt [MTOT*DM];      // V transposed per (b,h): [bh][64 d][2048 j]
__device__ float g_ctx[MTOT*DM];
__device__ float g_att[MTOT*DM];
__device__ float g_h  [MTOT*DM];
__device__ float g_ff1[(size_t)MTOT*DFF];
__device__ float g_ff2[MTOT*DM];
// transposed (K-major) weights (stored pre-rounded to tf32)
__device__ float g_Wqkv[3*DM*DM];     // [Wq^T | Wk^T | Wv^T] rows
__device__ float g_Wot[DM*DM];
__device__ float g_W1t[(size_t)DM*DFF];
__device__ float g_W2t[(size_t)DM*DFF];

// ======================= PTX helpers =========================================
__device__ __forceinline__ uint32_t smem_u32(const void* p) {
    uint32_t a;
    asm("{ .reg .u64 t; cvta.to.shared.u64 t, %1; cvt.u32.u64 %0, t; }" : "=r"(a) : "l"(p));
    return a;
}
__device__ __forceinline__ uint32_t f2tf32(float f) {
    uint32_t r;
    asm("cvt.rna.tf32.f32 %0, %1;" : "=r"(r) : "f"(f));
    return r;
}
__device__ __forceinline__ void mbar_init(uint32_t mbar, uint32_t cnt) {
    asm volatile("mbarrier.init.shared.b64 [%0], %1;" :: "r"(mbar), "r"(cnt) : "memory");
}
__device__ __forceinline__ void mbar_wait(uint32_t mbar, uint32_t parity) {
    asm volatile(
        "{\n\t.reg .pred P;\n"
        "WL_%=:\n\t"
        "mbarrier.try_wait.parity.shared.b64 P, [%0], %1;\n\t"
        "@!P bra WL_%=;\n\t}"
        :: "r"(mbar), "r"(parity) : "memory");
}
// 16-byte async copy gmem -> (pre-swizzled) smem address
__device__ __forceinline__ void cp16(uint32_t dst, const void* src) {
    asm volatile("cp.async.cg.shared.global [%0], [%1], 16;"
                 :: "r"(dst), "l"(src) : "memory");
}
__device__ __forceinline__ void cp_commit() {
    asm volatile("cp.async.commit_group;" ::: "memory");
}
__device__ __forceinline__ void cp_wait0() {
    asm volatile("cp.async.wait_group 0;" ::: "memory");
}
__device__ __forceinline__ void cp_wait1() {
    asm volatile("cp.async.wait_group 1;" ::: "memory");
}
// SW128 K-major smem descriptor (layout=2, version=1, SBO=64, LBO=1)
#define DESC_BASE_SW128 ((2ull<<61)|(1ull<<46)|(64ull<<32)|(1ull<<16))
__device__ __forceinline__ uint64_t make_desc(uint32_t addr) {
    return DESC_BASE_SW128 | ((uint64_t)(addr >> 4) & 0x3FFF);
}
#define SW128(off) ((off) ^ (((off) >> 3) & 0x70))

// tf32 idesc: dtype F32=1<<4, atype TF32=2<<7, btype TF32=2<<10, N/8<<17, M/16<<24
#define IDESC_TF32(M_, N_) ((1u<<4)|(2u<<7)|(2u<<10)|(((N_)/8u)<<17)|(((M_)/16u)<<24))

#if HAS_TCGEN05
__device__ __forceinline__ void mma_tf32_ss(uint32_t d_tmem, uint64_t a_desc,
                                            uint64_t b_desc, uint32_t idesc, uint32_t en) {
    asm volatile(
        "{\n\t.reg .pred p;\n\t"
        "setp.ne.u32 p, %4, 0;\n\t"
        "tcgen05.mma.cta_group::1.kind::tf32 [%0], %1, %2, %3, {%5,%5,%5,%5}, p;\n\t}"
        :: "r"(d_tmem), "l"(a_desc), "l"(b_desc), "r"(idesc), "r"(en), "r"(0u)
        : "memory");
}
// TS form: A from TMEM
__device__ __forceinline__ void mma_tf32_ts(uint32_t d_tmem, uint32_t a_tmem,
                                            uint64_t b_desc, uint32_t idesc, uint32_t en) {
    asm volatile(
        "{\n\t.reg .pred p;\n\t"
        "setp.ne.u32 p, %4, 0;\n\t"
        "tcgen05.mma.cta_group::1.kind::tf32 [%0], [%1], %2, %3, {%5,%5,%5,%5}, p;\n\t}"
        :: "r"(d_tmem), "r"(a_tmem), "l"(b_desc), "r"(idesc), "r"(en), "r"(0u)
        : "memory");
}
__device__ __forceinline__ void tmem_ld32(uint32_t* r, uint32_t addr) {
    asm volatile(
        "tcgen05.ld.sync.aligned.32x32b.x32.b32 "
        "{%0,%1,%2,%3,%4,%5,%6,%7,%8,%9,%10,%11,%12,%13,%14,%15,"
        "%16,%17,%18,%19,%20,%21,%22,%23,%24,%25,%26,%27,%28,%29,%30,%31}, [%32];"
        : "=r"(r[0]),"=r"(r[1]),"=r"(r[2]),"=r"(r[3]),"=r"(r[4]),"=r"(r[5]),
          "=r"(r[6]),"=r"(r[7]),"=r"(r[8]),"=r"(r[9]),"=r"(r[10]),"=r"(r[11]),
          "=r"(r[12]),"=r"(r[13]),"=r"(r[14]),"=r"(r[15]),"=r"(r[16]),"=r"(r[17]),
          "=r"(r[18]),"=r"(r[19]),"=r"(r[20]),"=r"(r[21]),"=r"(r[22]),"=r"(r[23]),
          "=r"(r[24]),"=r"(r[25]),"=r"(r[26]),"=r"(r[27]),"=r"(r[28]),"=r"(r[29]),
          "=r"(r[30]),"=r"(r[31])
        : "r"(addr));
}
__device__ __forceinline__ void tmem_st32(uint32_t addr, const uint32_t* r) {
    asm volatile(
        "tcgen05.st.sync.aligned.32x32b.x32.b32 [%0], "
        "{%1,%2,%3,%4,%5,%6,%7,%8,%9,%10,%11,%12,%13,%14,%15,%16,"
        "%17,%18,%19,%20,%21,%22,%23,%24,%25,%26,%27,%28,%29,%30,%31,%32};"
        :: "r"(addr),
           "r"(r[0]),"r"(r[1]),"r"(r[2]),"r"(r[3]),"r"(r[4]),"r"(r[5]),
           "r"(r[6]),"r"(r[7]),"r"(r[8]),"r"(r[9]),"r"(r[10]),"r"(r[11]),
           "r"(r[12]),"r"(r[13]),"r"(r[14]),"r"(r[15]),"r"(r[16]),"r"(r[17]),
           "r"(r[18]),"r"(r[19]),"r"(r[20]),"r"(r[21]),"r"(r[22]),"r"(r[23]),
           "r"(r[24]),"r"(r[25]),"r"(r[26]),"r"(r[27]),"r"(r[28]),"r"(r[29]),
           "r"(r[30]),"r"(r[31])
        : "memory");
}
#endif

// ======================= tcgen05 tf32 GEMM (R12 frozen: 2-stage pipeline) ====
#define GSM_BUF   32768              // A @ +0 (16KB), B @ +16KB per buffer
#define GSM_BOFF  16384
#define GSM_CTRL  (2*GSM_BUF)        // 64KB
#define GSM_SIZE  (GSM_CTRL + 1024)

#if HAS_TCGEN05
__device__ __forceinline__ void gemm_load_chunk_async(
    const float* __restrict__ A, const float* __restrict__ Bt, int K,
    int rowBase, int colBase, int k0, uint32_t buf, int tid)
{
#pragma unroll
    for (int t = 0; t < 4; ++t) {
        int i   = tid + t * 256;
        int row = i >> 3;
        int qq  = i & 7;
        cp16(buf + SW128((uint32_t)(row * 128 + qq * 16)),
             A + (size_t)(rowBase + row) * K + k0 + qq * 4);
    }
#pragma unroll
    for (int t = 0; t < 4; ++t) {
        int i   = tid + t * 256;
        int row = i >> 3;
        int qq  = i & 7;
        cp16(buf + GSM_BOFF + SW128((uint32_t)(row * 128 + qq * 16)),
             Bt + (size_t)(colBase + row) * K + k0 + qq * 4);
    }
    cp_commit();
}
#endif

__global__ __launch_bounds__(256) void tc_gemm_kernel(
    const float* __restrict__ A, const float* __restrict__ Bt,
    const float* __restrict__ b0, const float* __restrict__ b1,
    const float* __restrict__ b2,
    float* __restrict__ out0, float* __restrict__ out1, float* __restrict__ vt,
    int M, int N, int K, int mode)
{
#if HAS_TCGEN05
    extern __shared__ __align__(1024) char smem[];
    const uint32_t sbase = smem_u32(smem);
    const uint32_t mb0   = sbase + GSM_CTRL + 8;
    const uint32_t mb1   = sbase + GSM_CTRL + 16;
    const int tid = threadIdx.x;
    const int wid = tid >> 5;
    const int lid = tid & 31;

    const int rowBase = blockIdx.y * 128;
    const int colBase = blockIdx.x * 128;

    if (wid == 0) {
        asm volatile("tcgen05.alloc.cta_group::1.sync.aligned.shared::cta.b32 [%0], %1;"
                     :: "r"(sbase + GSM_CTRL), "r"(128u) : "memory");
        asm volatile("tcgen05.relinquish_alloc_permit.cta_group::1.sync.aligned;");
    }
    if (tid == 0) { mbar_init(mb0, 1); mbar_init(mb1, 1); }
    __syncthreads();
    uint32_t tmem_base;
    asm volatile("ld.shared.b32 %0, [%1];" : "=r"(tmem_base) : "r"(sbase + GSM_CTRL));

    const int nchunks = K >> 5;
    uint32_t pend0 = 0, pend1 = 0;

    gemm_load_chunk_async(A, Bt, K, rowBase, colBase, 0, sbase, tid);

    for (int c = 0; c < nchunks; ++c) {
        const int b = c & 1;

        if (c + 1 < nchunks) {
            if (b ^ 1) { if (pend1) mbar_wait(mb1, (pend1 - 1) & 1); }
            else       { if (pend0) mbar_wait(mb0, (pend0 - 1) & 1); }
            gemm_load_chunk_async(A, Bt, K, rowBase, colBase, (c + 1) << 5,
                                  sbase + (uint32_t)(b ^ 1) * GSM_BUF, tid);
            cp_wait1();
        } else {
            cp_wait0();
        }
        asm volatile("fence.proxy.async.shared::cta;" ::: "memory");
        __syncthreads();

        if (tid == 0) {
            const uint32_t buf = sbase + (uint32_t)b * GSM_BUF;
            uint64_t ad = make_desc(buf);
            uint64_t bd = make_desc(buf + GSM_BOFF);
#pragma unroll
            for (int s = 0; s < 4; ++s)
                mma_tf32_ss(tmem_base, ad + s * 2, bd + s * 2, IDESC_TF32(128,128),
                            (c > 0 || s > 0) ? 1u : 0u);
            asm volatile(
                "tcgen05.commit.cta_group::1.mbarrier::arrive::one.shared::cluster.b64 [%0];"
                :: "r"(b ? mb1 : mb0) : "memory");
        }
        if (b) ++pend1; else ++pend0;
    }

    if (pend0) mbar_wait(mb0, (pend0 - 1) & 1);
    if (pend1) mbar_wait(mb1, (pend1 - 1) & 1);
    asm volatile("tcgen05.fence::after_thread_sync;" ::: "memory");

    // ---- epilogue ----
    {
        const int sub  = wid & 3;
        const int half = wid >> 2;
        const int row  = rowBase + sub * 32 + lid;
#pragma unroll
        for (int g = 0; g < 2; ++g) {
            const int colOff = half * 64 + g * 32;
            uint32_t r[32];
            tmem_ld32(r, tmem_base + colOff);
            asm volatile("tcgen05.wait::ld.sync.aligned;" ::: "memory");

            if (mode == 2) {
                const int cglob = colBase + colOff;
                const int which = cglob >> 10;
                const int cloc  = cglob & 1023;
                if (which < 2) {
                    float* out = which ? out1 : out0;
                    const float* bias = which ? b1 : b0;
                    float* crow = out + (size_t)row * DM + cloc;
#pragma unroll
                    for (int j4 = 0; j4 < 8; ++j4) {
                        float4 o;
                        o.x = __uint_as_float(r[j4*4+0]) + bias[cloc + j4*4+0];
                        o.y = __uint_as_float(r[j4*4+1]) + bias[cloc + j4*4+1];
                        o.z = __uint_as_float(r[j4*4+2]) + bias[cloc + j4*4+2];
                        o.w = __uint_as_float(r[j4*4+3]) + bias[cloc + j4*4+3];
                        *(float4*)(crow + j4 * 4) = o;
                    }
                } else {
                    const int bb = row >> 11;
                    const int j  = row & 2047;
                    float* base = vt + ((size_t)(bb * NH + (cloc >> 6)) * DK
                                        + (cloc & 63)) * SEQ + j;
#pragma unroll
                    for (int cc = 0; cc < 32; ++cc)
                        base[(size_t)cc * SEQ] = __uint_as_float(r[cc]) + b2[cloc + cc];
                }
            } else {
                float* crow = out0 + (size_t)row * N + colBase + colOff;
#pragma unroll
                for (int j4 = 0; j4 < 8; ++j4) {
                    float4 o;
                    float v0 = __uint_as_float(r[j4*4+0]) + b0[colBase + colOff + j4*4+0];
                    float v1 = __uint_as_float(r[j4*4+1]) + b0[colBase + colOff + j4*4+1];
                    float v2 = __uint_as_float(r[j4*4+2]) + b0[colBase + colOff + j4*4+2];
                    float v3 = __uint_as_float(r[j4*4+3]) + b0[colBase + colOff + j4*4+3];
                    if (mode == 1) {
                        v0 = 0.5f * v0 * (1.f + erff(v0 * 0.70710678118654752440f));
                        v1 = 0.5f * v1 * (1.f + erff(v1 * 0.70710678118654752440f));
                        v2 = 0.5f * v2 * (1.f + erff(v2 * 0.70710678118654752440f));
                        v3 = 0.5f * v3 * (1.f + erff(v3 * 0.70710678118654752440f));
                    }
                    o.x = v0; o.y = v1; o.z = v2; o.w = v3;
                    *(float4*)(crow + j4 * 4) = o;
                }
            }
        }
    }
    asm volatile("tcgen05.fence::before_thread_sync;" ::: "memory");
    __syncthreads();
    if (wid == 0) {
        asm volatile("tcgen05.dealloc.cta_group::1.sync.aligned.b32 %0, %1;"
                     :: "r"(tmem_base), "r"(128u));
    }
#endif
}

// ======================= tcgen05 tf32 flash attention (prefetched) ===========
// Single K / Vt buffers; K(j+1) prefetched after MMA1(j), Vt(j+1) after MMA2(j).
// Commit order: Q, K0, V0, K1, V1, ... -> wait-for-K = wait_group 1,
// wait-for-V = wait_group 1 (K(j+1) pending) or 0 on last iteration.
#define ASM_Q    0
#define ASM_K    32768
#define ASM_VT   65536
#define ASM_CTRL 98304
#define ASM_SIZE (98304 + 1024)

#if HAS_TCGEN05
__device__ __forceinline__ void attn_load_k(const float* __restrict__ kb,
                                            uint32_t sbase, int j0, int tid) {
#pragma unroll
    for (int t = 0; t < 8; ++t) {
        int i   = tid + t * 256;
        int row = i >> 4;
        int d0  = (i & 15) * 4;
        cp16(sbase + ASM_K + ((uint32_t)(d0 >> 5)) * 16384u
             + SW128((uint32_t)(row * 128 + (d0 & 31) * 4)),
             kb + (size_t)(j0 + row) * DM + d0);
    }
    cp_commit();
}
__device__ __forceinline__ void attn_load_vt(const float* __restrict__ vtb,
                                             uint32_t sbase, int j0, int tid) {
#pragma unroll
    for (int t = 0; t < 8; ++t) {
        int i    = tid + t * 256;
        int rowd = i >> 5;
        int jj   = (i & 31) * 4;
        cp16(sbase + ASM_VT + ((uint32_t)(jj >> 5)) * 8192u
             + SW128((uint32_t)(rowd * 128 + (jj & 31) * 4)),
             vtb + (size_t)rowd * SEQ + j0 + jj);
    }
    cp_commit();
}
#endif

__global__ __launch_bounds__(256, 2) void tc_attention_kernel(
    const float* __restrict__ q, const float* __restrict__ k,
    const float* __restrict__ vt, float* __restrict__ ctx)
{
#if HAS_TCGEN05
    extern __shared__ __align__(1024) char smem[];
    const uint32_t sbase = smem_u32(smem);
    const uint32_t mbar  = sbase + ASM_CTRL + 8;
    const int tid = threadIdx.x;
    const int wid = tid >> 5;
    const int lid = tid & 31;

    const int bh = blockIdx.y;
    const int b  = bh / NH;
    const int h  = bh % NH;
    const int q0 = blockIdx.x * 128;

    const float* qb  = q  + (size_t)(b * SEQ + q0) * DM + h * DK;
    const float* kb  = k  + (size_t)b * SEQ * DM + h * DK;
    const float* vtb = vt + (size_t)bh * DK * SEQ;

    if (wid == 0) {
        asm volatile("tcgen05.alloc.cta_group::1.sync.aligned.shared::cta.b32 [%0], %1;"
                     :: "r"(sbase + ASM_CTRL), "r"(256u) : "memory");
        asm volatile("tcgen05.relinquish_alloc_permit.cta_group::1.sync.aligned;");
    }
    if (tid == 0) mbar_init(mbar, 1);
    __syncthreads();
    uint32_t tmem_base;
    asm volatile("ld.shared.b32 %0, [%1];" : "=r"(tmem_base) : "r"(sbase + ASM_CTRL));
    const uint32_t tS = tmem_base;
    const uint32_t tO = tmem_base + 128;

    // ---- Q load (own cp.async group, oldest) ----
#pragma unroll
    for (int t = 0; t < 8; ++t) {
        int i   = tid + t * 256;
        int row = i >> 4;
        int d0  = (i & 15) * 4;
        cp16(sbase + ASM_Q + ((uint32_t)(d0 >> 5)) * 16384u
             + SW128((uint32_t)(row * 128 + (d0 & 31) * 4)),
             qb + (size_t)row * DM + d0);
    }
    cp_commit();

    const int sub  = wid & 3;
    const int half = wid >> 2;
    const int r    = sub * 32 + lid;
    const uint32_t st_off = ((uint32_t)sub) << 21;

    float lsum = 0.f;
    uint32_t cnt = 0;

    const uint64_t dQ  = make_desc(sbase + ASM_Q);
    const uint64_t dK  = make_desc(sbase + ASM_K);
    const uint64_t dVt = make_desc(sbase + ASM_VT);

    // ---- prologue: K(0), Vt(0) ----
    attn_load_k (kb,  sbase, 0, tid);
    attn_load_vt(vtb, sbase, 0, tid);

    for (int j0 = 0; j0 < SEQ; j0 += 128) {
        const int more = (j0 + 128 < SEQ);

        // (a) K(j) landed (1 newer group: Vt(j))
        cp_wait1();
        asm volatile("fence.proxy.async.shared::cta;" ::: "memory");
        __syncthreads();

        // (c) MMA1: S = Q @ K^T
        if (tid == 0) {
#pragma unroll
            for (int s = 0; s < 8; ++s) {
                uint64_t off = (uint64_t)((s >> 2) * 1024 + (s & 3) * 2);
                mma_tf32_ss(tS, dQ + off, dK + off, IDESC_TF32(128,128), s > 0 ? 1u : 0u);
            }
            asm volatile(
                "tcgen05.commit.cta_group::1.mbarrier::arrive::one.shared::cluster.b64 [%0];"
                :: "r"(mbar) : "memory");
        }
        mbar_wait(mbar, cnt & 1); ++cnt;
        asm volatile("tcgen05.fence::after_thread_sync;" ::: "memory");

        // (d) prefetch K(j+1) — K smem free (MMA1 done); overlaps softmax+MMA2
        if (more) attn_load_k(kb, sbase, j0 + 128, tid);

        // (e) softmax: P = exp(S/8) back into TMEM
#pragma unroll
        for (int g = 0; g < 2; ++g) {
            const int c0 = half * 64 + g * 32;
            uint32_t sreg[32];
            tmem_ld32(sreg, tS + c0);
            asm volatile("tcgen05.wait::ld.sync.aligned;" ::: "memory");
#pragma unroll
            for (int j = 0; j < 32; ++j) {
                float p = __expf(__uint_as_float(sreg[j]) * 0.125f);
                lsum += p;
                sreg[j] = f2tf32(p);
            }
            tmem_st32(tS + c0 + st_off, sreg);
        }
        asm volatile("tcgen05.wait::st.sync.aligned;" ::: "memory");
        asm volatile("tcgen05.fence::before_thread_sync;" ::: "memory");

        // (f) Vt(j) landed (newer: K(j+1) if issued)
        if (more) cp_wait1(); else cp_wait0();
        asm volatile("fence.proxy.async.shared::cta;" ::: "memory");
        __syncthreads();

        // (g) MMA2: O += P(TMEM) @ Vt^T
        if (tid == 0) {
            asm volatile("tcgen05.fence::after_thread_sync;" ::: "memory");
#pragma unroll
            for (int s = 0; s < 16; ++s) {
                uint64_t offB = (uint64_t)((s >> 2) * 512 + (s & 3) * 2);
                mma_tf32_ts(tO, tS + s * 8, dVt + offB, IDESC_TF32(128,64),
                            (j0 > 0 || s > 0) ? 1u : 0u);
            }
            asm volatile(
                "tcgen05.commit.cta_group::1.mbarrier::arrive::one.shared::cluster.b64 [%0];"
                :: "r"(mbar) : "memory");
        }
        mbar_wait(mbar, cnt & 1); ++cnt;

        // (h) prefetch Vt(j+1) — Vt smem free (MMA2 done); overlaps next MMA1
        if (more) attn_load_vt(vtb, sbase, j0 + 128, tid);
    }

    asm volatile("tcgen05.fence::after_thread_sync;" ::: "memory");
    __syncthreads();

    // ---- combine row sums across the two column-half warps (reuse K area) ----
    {
        float* l_arr = (float*)(smem + ASM_K);
        l_arr[half * 128 + r] = lsum;
    }
    __syncthreads();
    float ltot;
    {
        float* l_arr = (float*)(smem + ASM_K);
        ltot = l_arr[r] + l_arr[128 + r];
    }
    const float inv = 1.f / ltot;

    {
        const int c0 = half * 32;
        uint32_t oreg[32];
        tmem_ld32(oreg, tO + c0);
        asm volatile("tcgen05.wait::ld.sync.aligned;" ::: "memory");
        float* orow = ctx + (size_t)(b * SEQ + q0 + r) * DM + h * DK + c0;
#pragma unroll
        for (int j4 = 0; j4 < 8; ++j4) {
            float4 o;
            o.x = __uint_as_float(oreg[j4*4+0]) * inv;
            o.y = __uint_as_float(oreg[j4*4+1]) * inv;
            o.z = __uint_as_float(oreg[j4*4+2]) * inv;
            o.w = __uint_as_float(oreg[j4*4+3]) * inv;
            *(float4*)(orow + j4 * 4) = o;
        }
    }
    asm volatile("tcgen05.fence::before_thread_sync;" ::: "memory");
    __syncthreads();
    if (wid == 0) {
        asm volatile("tcgen05.dealloc.cta_group::1.sync.aligned.b32 %0, %1;"
                     :: "r"(tmem_base), "r"(256u));
    }
#endif
}

// ======================= fused weight transpose (ALL 6 in one launch) ========
__global__ __launch_bounds__(256) void transpose_all_kernel(
    const float* __restrict__ Wq, const float* __restrict__ Wk,
    const float* __restrict__ Wv, const float* __restrict__ Wo,
    const float* __restrict__ W1, const float* __restrict__ W2,
    float* __restrict__ Wqkv, float* __restrict__ Wot,
    float* __restrict__ W1t,  float* __restrict__ W2t)
{
    __shared__ float t[32][33];
    const int bid = blockIdx.x;
    const float* in; float* out; int R, C, idx;

    if (bid < 4096) {
        R = DM; C = DM; idx = bid & 1023;
        const int j = bid >> 10;
        in  = (j == 0) ? Wq : (j == 1) ? Wk : (j == 2) ? Wv : Wo;
        out = (j == 3) ? Wot : Wqkv + (size_t)j * DM * DM;
    } else if (bid < 8192) {
        R = DM; C = DFF; idx = bid - 4096;
        in = W1; out = W1t;
    } else {
        R = DFF; C = DM; idx = bid - 8192;
        in = W2; out = W2t;
    }
    const int Ct = C >> 5;
    const int c0 = (idx % Ct) * 32;
    const int r0 = (idx / Ct) * 32;
    const int x = threadIdx.x & 31;
    const int y = threadIdx.x >> 5;
#pragma unroll
    for (int i = y; i < 32; i += 8)
        t[i][x] = in[(size_t)(r0 + i) * C + c0 + x];
    __syncthreads();
#pragma unroll
    for (int i = y; i < 32; i += 8)
        out[(size_t)(c0 + i) * R + r0 + x] = __uint_as_float(f2tf32(t[x][i]));
}

// ======================= fused residual + LayerNorm ==========================
__global__ __launch_bounds__(256) void ln_residual_kernel(
    const float* __restrict__ X, const float* __restrict__ Y,
    const float* __restrict__ g, const float* __restrict__ be,
    float* __restrict__ out)
{
    __shared__ float buf[DM];
    __shared__ float red1[256], red2[256];

    const int row = blockIdx.x;
    const int tid = threadIdx.x;
    const size_t base = (size_t)row * DM;

    float s = 0.f, s2 = 0.f;
#pragma unroll
    for (int c = tid; c < DM; c += 256) {
        float vv = X[base + c] + Y[base + c];
        buf[c] = vv;
        s  += vv;
        s2 += vv * vv;
    }
    red1[tid] = s; red2[tid] = s2;
    __syncthreads();
    for (int off = 128; off > 0; off >>= 1) {
        if (tid < off) {
            red1[tid] += red1[tid + off];
            red2[tid] += red2[tid + off];
        }
        __syncthreads();
    }
    const float mu  = red1[0] * (1.f / DM);
    const float var = red2[0] * (1.f / DM) - mu * mu;
    const float rs  = rsqrtf(var + 1e-5f);

#pragma unroll
    for (int c = tid; c < DM; c += 256)
        out[base + c] = (buf[c] - mu) * rs * g[c] + be[c];
}

// ======================= launch ==============================================
extern "C" void kernel_launch(void* const* d_in, const int* in_sizes, int n_in,
                              void* d_out, int out_size)
{
    const float* x  = (const float*)d_in[0];
    const float* Wq = (const float*)d_in[1];  const float* bq = (const float*)d_in[2];
    const float* Wk = (const float*)d_in[3];  const float* bk = (const float*)d_in[4];
    const float* Wv = (const float*)d_in[5];  const float* bv = (const float*)d_in[6];
    const float* Wo = (const float*)d_in[7];  const float* bo = (const float*)d_in[8];
    const float* W1 = (const float*)d_in[9];  const float* b1 = (const float*)d_in[10];
    const float* W2 = (const float*)d_in[11]; const float* b2 = (const float*)d_in[12];
    const float* g1 = (const float*)d_in[13]; const float* be1 = (const float*)d_in[14];
    const float* g2 = (const float*)d_in[15]; const float* be2 = (const float*)d_in[16];

    float *q, *k, *vt, *ctx, *att, *h, *ff1, *ff2;
    float *Wqkv, *Wot, *W1t, *W2t;
    cudaGetSymbolAddress((void**)&q,    g_q);
    cudaGetSymbolAddress((void**)&k,    g_k);
    cudaGetSymbolAddress((void**)&vt,   g_vt);
    cudaGetSymbolAddress((void**)&ctx,  g_ctx);
    cudaGetSymbolAddress((void**)&att,  g_att);
    cudaGetSymbolAddress((void**)&h,    g_h);
    cudaGetSymbolAddress((void**)&ff1,  g_ff1);
    cudaGetSymbolAddress((void**)&ff2,  g_ff2);
    cudaGetSymbolAddress((void**)&Wqkv, g_Wqkv);
    cudaGetSymbolAddress((void**)&Wot,  g_Wot);
    cudaGetSymbolAddress((void**)&W1t,  g_W1t);
    cudaGetSymbolAddress((void**)&W2t,  g_W2t);

    static int smem_set = 0;
    if (!smem_set) {
        cudaFuncSetAttribute(tc_attention_kernel,
                             cudaFuncAttributeMaxDynamicSharedMemorySize, ASM_SIZE);
        cudaFuncSetAttribute(tc_gemm_kernel,
                             cudaFuncAttributeMaxDynamicSharedMemorySize, GSM_SIZE);
        smem_set = 1;
    }

    // ---- all 6 weight transposes (tf32-rounded) in ONE launch ----
    transpose_all_kernel<<<12288, 256>>>(Wq, Wk, Wv, Wo, W1, W2,
                                         Wqkv, Wot, W1t, W2t);

    const dim3 gQKV (3*DM / 128, MTOT / 128);   // (24, 32)
    const dim3 gProj(DM / 128,   MTOT / 128);   // (8, 32)
    const dim3 gFF1 (DFF / 128,  MTOT / 128);   // (32, 32)

    // fused QKV projection (V written transposed)
    tc_gemm_kernel<<<gQKV, 256, GSM_SIZE>>>(x, Wqkv, bq, bk, bv, q, k, vt, MTOT, 3*DM, DM, 2);

    // attention (tf32 tensor cores, P in TMEM, prefetched K/Vt)
    tc_attention_kernel<<<dim3(SEQ / 128, BATCH * NH), 256, ASM_SIZE>>>(q, k, vt, ctx);

    // output projection
    tc_gemm_kernel<<<gProj, 256, GSM_SIZE>>>(ctx, Wot, bo, 0, 0, att, 0, 0, MTOT, DM, DM, 0);

    // residual + LN1 -> h
    ln_residual_kernel<<<MTOT, 256>>>(x, att, g1, be1, h);

    // FFN
    tc_gemm_kernel<<<gFF1, 256, GSM_SIZE>>>(h, W1t, b1, 0, 0, ff1, 0, 0, MTOT, DFF, DM, 1);
    tc_gemm_kernel<<<gProj, 256, GSM_SIZE>>>(ff1, W2t, b2, 0, 0, ff2, 0, 0, MTOT, DM, DFF, 0);

    // residual + LN2 -> output
    ln_residual_kernel<<<MTOT, 256>>>(h, ff2, g2, be2, (float*)d_out);
}

// round 17
// speedup vs baseline: 1.0909x; 1.0214x over previous
#include <cuda_runtime.h>
#include <cuda_bf16.h>
#include <math.h>
#include <stdint.h>

#define BATCH 2
#define SEQ   2048
#define DM    1024
#define NH    16
#define DK    64
#define DFF   4096
#define MTOT  (BATCH*SEQ)   // 4096 rows

#if defined(__CUDA_ARCH__) && defined(__CUDA_ARCH_FEAT_SM103_ALL)
#define HAS_TCGEN05 1
#else
#define HAS_TCGEN05 0
#endif

// ---------------- scratch (device globals; no allocations allowed) ----------
__device__ float g_q  [MTOT*DM];
__device__ float g_k  [MTOT*DM];
__device__ __nv_bfloat16 g_vt[MTOT*DM];   // V^T per (b,h): [bh][64 d][2048 j], bf16
__device__ float g_ctx[MTOT*DM];
__device__ float g_att[MTOT*DM];
__device__ float g_h  [MTOT*DM];
__device__ float g_ff1[(size_t)MTOT*DFF];
__device__ float g_ff2[MTOT*DM];
// transposed (K-major) weights (stored pre-rounded to tf32)
__device__ float g_Wqkv[3*DM*DM];
__device__ float g_Wot[DM*DM];
__device__ float g_W1t[(size_t)DM*DFF];
__device__ float g_W2t[(size_t)DM*DFF];

// ======================= PTX helpers =========================================
__device__ __forceinline__ uint32_t smem_u32(const void* p) {
    uint32_t a;
    asm("{ .reg .u64 t; cvta.to.shared.u64 t, %1; cvt.u32.u64 %0, t; }" : "=r"(a) : "l"(p));
    return a;
}
__device__ __forceinline__ uint32_t f2tf32(float f) {
    uint32_t r;
    asm("cvt.rna.tf32.f32 %0, %1;" : "=r"(r) : "f"(f));
    return r;
}
__device__ __forceinline__ void mbar_init(uint32_t mbar, uint32_t cnt) {
    asm volatile("mbarrier.init.shared.b64 [%0], %1;" :: "r"(mbar), "r"(cnt) : "memory");
}
__device__ __forceinline__ void mbar_wait(uint32_t mbar, uint32_t parity) {
    asm volatile(
        "{\n\t.reg .pred P;\n"
        "WL_%=:\n\t"
        "mbarrier.try_wait.parity.shared.b64 P, [%0], %1;\n\t"
        "@!P bra WL_%=;\n\t}"
        :: "r"(mbar), "r"(parity) : "memory");
}
__device__ __forceinline__ void cp16(uint32_t dst, const void* src) {
    asm volatile("cp.async.cg.shared.global [%0], [%1], 16;"
                 :: "r"(dst), "l"(src) : "memory");
}
__device__ __forceinline__ void cp_commit() {
    asm volatile("cp.async.commit_group;" ::: "memory");
}
__device__ __forceinline__ void cp_wait0() {
    asm volatile("cp.async.wait_group 0;" ::: "memory");
}
__device__ __forceinline__ void cp_wait1() {
    asm volatile("cp.async.wait_group 1;" ::: "memory");
}
// SW128 K-major smem descriptor (layout=2, version=1, SBO=64, LBO=1)
#define DESC_BASE_SW128 ((2ull<<61)|(1ull<<46)|(64ull<<32)|(1ull<<16))
__device__ __forceinline__ uint64_t make_desc(uint32_t addr) {
    return DESC_BASE_SW128 | ((uint64_t)(addr >> 4) & 0x3FFF);
}
#define SW128(off) ((off) ^ (((off) >> 3) & 0x70))

// idescs: dtype F32=1<<4; tf32 a/b=2; bf16 a/b=1; N/8<<17, M/16<<24
#define IDESC_TF32(M_, N_) ((1u<<4)|(2u<<7)|(2u<<10)|(((N_)/8u)<<17)|(((M_)/16u)<<24))
#define IDESC_BF16(M_, N_) ((1u<<4)|(1u<<7)|(1u<<10)|(((N_)/8u)<<17)|(((M_)/16u)<<24))

#if HAS_TCGEN05
__device__ __forceinline__ void mma_tf32_ss(uint32_t d_tmem, uint64_t a_desc,
                                            uint64_t b_desc, uint32_t idesc, uint32_t en) {
    asm volatile(
        "{\n\t.reg .pred p;\n\t"
        "setp.ne.u32 p, %4, 0;\n\t"
        "tcgen05.mma.cta_group::1.kind::tf32 [%0], %1, %2, %3, {%5,%5,%5,%5}, p;\n\t}"
        :: "r"(d_tmem), "l"(a_desc), "l"(b_desc), "r"(idesc), "r"(en), "r"(0u)
        : "memory");
}
__device__ __forceinline__ void mma_bf16_ss(uint32_t d_tmem, uint64_t a_desc,
                                            uint64_t b_desc, uint32_t idesc, uint32_t en) {
    asm volatile(
        "{\n\t.reg .pred p;\n\t"
        "setp.ne.u32 p, %4, 0;\n\t"
        "tcgen05.mma.cta_group::1.kind::f16 [%0], %1, %2, %3, {%5,%5,%5,%5}, p;\n\t}"
        :: "r"(d_tmem), "l"(a_desc), "l"(b_desc), "r"(idesc), "r"(en), "r"(0u)
        : "memory");
}
__device__ __forceinline__ void tmem_ld32(uint32_t* r, uint32_t addr) {
    asm volatile(
        "tcgen05.ld.sync.aligned.32x32b.x32.b32 "
        "{%0,%1,%2,%3,%4,%5,%6,%7,%8,%9,%10,%11,%12,%13,%14,%15,"
        "%16,%17,%18,%19,%20,%21,%22,%23,%24,%25,%26,%27,%28,%29,%30,%31}, [%32];"
        : "=r"(r[0]),"=r"(r[1]),"=r"(r[2]),"=r"(r[3]),"=r"(r[4]),"=r"(r[5]),
          "=r"(r[6]),"=r"(r[7]),"=r"(r[8]),"=r"(r[9]),"=r"(r[10]),"=r"(r[11]),
          "=r"(r[12]),"=r"(r[13]),"=r"(r[14]),"=r"(r[15]),"=r"(r[16]),"=r"(r[17]),
          "=r"(r[18]),"=r"(r[19]),"=r"(r[20]),"=r"(r[21]),"=r"(r[22]),"=r"(r[23]),
          "=r"(r[24]),"=r"(r[25]),"=r"(r[26]),"=r"(r[27]),"=r"(r[28]),"=r"(r[29]),
          "=r"(r[30]),"=r"(r[31])
        : "r"(addr));
}
#endif

// ======================= tcgen05 tf32 GEMM (R12 frozen: 2-stage pipeline) ====
#define GSM_BUF   32768
#define GSM_BOFF  16384
#define GSM_CTRL  (2*GSM_BUF)
#define GSM_SIZE  (GSM_CTRL + 1024)

#if HAS_TCGEN05
__device__ __forceinline__ void gemm_load_chunk_async(
    const float* __restrict__ A, const float* __restrict__ Bt, int K,
    int rowBase, int colBase, int k0, uint32_t buf, int tid)
{
#pragma unroll
    for (int t = 0; t < 4; ++t) {
        int i   = tid + t * 256;
        int row = i >> 3;
        int qq  = i & 7;
        cp16(buf + SW128((uint32_t)(row * 128 + qq * 16)),
             A + (size_t)(rowBase + row) * K + k0 + qq * 4);
    }
#pragma unroll
    for (int t = 0; t < 4; ++t) {
        int i   = tid + t * 256;
        int row = i >> 3;
        int qq  = i & 7;
        cp16(buf + GSM_BOFF + SW128((uint32_t)(row * 128 + qq * 16)),
             Bt + (size_t)(colBase + row) * K + k0 + qq * 4);
    }
    cp_commit();
}
#endif

__global__ __launch_bounds__(256) void tc_gemm_kernel(
    const float* __restrict__ A, const float* __restrict__ Bt,
    const float* __restrict__ b0, const float* __restrict__ b1,
    const float* __restrict__ b2,
    float* __restrict__ out0, float* __restrict__ out1,
    __nv_bfloat16* __restrict__ vt,
    int M, int N, int K, int mode)
{
#if HAS_TCGEN05
    extern __shared__ __align__(1024) char smem[];
    const uint32_t sbase = smem_u32(smem);
    const uint32_t mb0   = sbase + GSM_CTRL + 8;
    const uint32_t mb1   = sbase + GSM_CTRL + 16;
    const int tid = threadIdx.x;
    const int wid = tid >> 5;
    const int lid = tid & 31;

    const int rowBase = blockIdx.y * 128;
    const int colBase = blockIdx.x * 128;

    if (wid == 0) {
        asm volatile("tcgen05.alloc.cta_group::1.sync.aligned.shared::cta.b32 [%0], %1;"
                     :: "r"(sbase + GSM_CTRL), "r"(128u) : "memory");
        asm volatile("tcgen05.relinquish_alloc_permit.cta_group::1.sync.aligned;");
    }
    if (tid == 0) { mbar_init(mb0, 1); mbar_init(mb1, 1); }
    __syncthreads();
    uint32_t tmem_base;
    asm volatile("ld.shared.b32 %0, [%1];" : "=r"(tmem_base) : "r"(sbase + GSM_CTRL));

    const int nchunks = K >> 5;
    uint32_t pend0 = 0, pend1 = 0;

    gemm_load_chunk_async(A, Bt, K, rowBase, colBase, 0, sbase, tid);

    for (int c = 0; c < nchunks; ++c) {
        const int b = c & 1;

        if (c + 1 < nchunks) {
            if (b ^ 1) { if (pend1) mbar_wait(mb1, (pend1 - 1) & 1); }
            else       { if (pend0) mbar_wait(mb0, (pend0 - 1) & 1); }
            gemm_load_chunk_async(A, Bt, K, rowBase, colBase, (c + 1) << 5,
                                  sbase + (uint32_t)(b ^ 1) * GSM_BUF, tid);
            cp_wait1();
        } else {
            cp_wait0();
        }
        asm volatile("fence.proxy.async.shared::cta;" ::: "memory");
        __syncthreads();

        if (tid == 0) {
            const uint32_t buf = sbase + (uint32_t)b * GSM_BUF;
            uint64_t ad = make_desc(buf);
            uint64_t bd = make_desc(buf + GSM_BOFF);
#pragma unroll
            for (int s = 0; s < 4; ++s)
                mma_tf32_ss(tmem_base, ad + s * 2, bd + s * 2, IDESC_TF32(128,128),
                            (c > 0 || s > 0) ? 1u : 0u);
            asm volatile(
                "tcgen05.commit.cta_group::1.mbarrier::arrive::one.shared::cluster.b64 [%0];"
                :: "r"(b ? mb1 : mb0) : "memory");
        }
        if (b) ++pend1; else ++pend0;
    }

    if (pend0) mbar_wait(mb0, (pend0 - 1) & 1);
    if (pend1) mbar_wait(mb1, (pend1 - 1) & 1);
    asm volatile("tcgen05.fence::after_thread_sync;" ::: "memory");

    // ---- epilogue ----
    {
        const int sub  = wid & 3;
        const int half = wid >> 2;
        const int row  = rowBase + sub * 32 + lid;
#pragma unroll
        for (int g = 0; g < 2; ++g) {
            const int colOff = half * 64 + g * 32;
            uint32_t r[32];
            tmem_ld32(r, tmem_base + colOff);
            asm volatile("tcgen05.wait::ld.sync.aligned;" ::: "memory");

            if (mode == 2) {
                const int cglob = colBase + colOff;
                const int which = cglob >> 10;
                const int cloc  = cglob & 1023;
                if (which < 2) {
                    float* out = which ? out1 : out0;
                    const float* bias = which ? b1 : b0;
                    float* crow = out + (size_t)row * DM + cloc;
#pragma unroll
                    for (int j4 = 0; j4 < 8; ++j4) {
                        float4 o;
                        o.x = __uint_as_float(r[j4*4+0]) + bias[cloc + j4*4+0];
                        o.y = __uint_as_float(r[j4*4+1]) + bias[cloc + j4*4+1];
                        o.z = __uint_as_float(r[j4*4+2]) + bias[cloc + j4*4+2];
                        o.w = __uint_as_float(r[j4*4+3]) + bias[cloc + j4*4+3];
                        *(float4*)(crow + j4 * 4) = o;
                    }
                } else {
                    // V transposed write: vt[bh][d][j] (bf16, rna)
                    const int bb = row >> 11;
                    const int j  = row & 2047;
                    __nv_bfloat16* base = vt + ((size_t)(bb * NH + (cloc >> 6)) * DK
                                                + (cloc & 63)) * SEQ + j;
#pragma unroll
                    for (int cc = 0; cc < 32; ++cc)
                        base[(size_t)cc * SEQ] =
                            __float2bfloat16_rn(__uint_as_float(r[cc]) + b2[cloc + cc]);
                }
            } else {
                float* crow = out0 + (size_t)row * N + colBase + colOff;
#pragma unroll
                for (int j4 = 0; j4 < 8; ++j4) {
                    float4 o;
                    float v0 = __uint_as_float(r[j4*4+0]) + b0[colBase + colOff + j4*4+0];
                    float v1 = __uint_as_float(r[j4*4+1]) + b0[colBase + colOff + j4*4+1];
                    float v2 = __uint_as_float(r[j4*4+2]) + b0[colBase + colOff + j4*4+2];
                    float v3 = __uint_as_float(r[j4*4+3]) + b0[colBase + colOff + j4*4+3];
                    if (mode == 1) {
                        v0 = 0.5f * v0 * (1.f + erff(v0 * 0.70710678118654752440f));
                        v1 = 0.5f * v1 * (1.f + erff(v1 * 0.70710678118654752440f));
                        v2 = 0.5f * v2 * (1.f + erff(v2 * 0.70710678118654752440f));
                        v3 = 0.5f * v3 * (1.f + erff(v3 * 0.70710678118654752440f));
                    }
                    o.x = v0; o.y = v1; o.z = v2; o.w = v3;
                    *(float4*)(crow + j4 * 4) = o;
                }
            }
        }
    }
    asm volatile("tcgen05.fence::before_thread_sync;" ::: "memory");
    __syncthreads();
    if (wid == 0) {
        asm volatile("tcgen05.dealloc.cta_group::1.sync.aligned.b32 %0, %1;"
                     :: "r"(tmem_base), "r"(128u));
    }
#endif
}

// ======================= tcgen05 flash attention (fused-commit, bf16 P/V) ====
// TMEM: S 128 cols + O 64 cols (alloc 256). SMEM: Q 32K; K/P 2-slot 2x32K
// (slot j&1: K(j) fp32 until MMA1(j), then P(j) bf16); V 16K bf16.
// Per iter j>=1: ONE commit covers MMA2(j-1) [bf16 SS: P(j-1),V(j-1)] +
// MMA1(j) [tf32 SS: Q,K(j)]. Then prefetch K(j+1)+V(j), softmax S(j)->P(j).
#define ASM_Q    0
#define ASM_KP   32768            // 2 slots x 32KB
#define ASM_V    98304            // 16KB bf16
#define ASM_CTRL 114688
#define ASM_SIZE (114688 + 64)

#if HAS_TCGEN05
__device__ __forceinline__ void attn_load_k(const float* __restrict__ kb,
                                            uint32_t slotbase, int j0, int tid) {
#pragma unroll
    for (int t = 0; t < 8; ++t) {
        int i   = tid + t * 256;
        int row = i >> 4;
        int d0  = (i & 15) * 4;
        cp16(slotbase + ((uint32_t)(d0 >> 5)) * 16384u
             + SW128((uint32_t)(row * 128 + (d0 & 31) * 4)),
             kb + (size_t)(j0 + row) * DM + d0);
    }
}
__device__ __forceinline__ void attn_load_v(const __nv_bfloat16* __restrict__ vtb,
                                            uint32_t sbase, int j0, int tid) {
    // 64 d rows x 128 j bf16 = 16KB; 2 subtiles of 8KB (j 0-63 / 64-127)
#pragma unroll
    for (int t = 0; t < 4; ++t) {
        int i    = tid + t * 256;        // 1024 cp16s of 16B (8 bf16)
        int rowd = i >> 4;               // 16 per row
        int jj   = (i & 15);             // 16B unit within row
        cp16(sbase + ASM_V + ((uint32_t)(jj >> 3)) * 8192u
             + SW128((uint32_t)(rowd * 128 + (jj & 7) * 16)),
             vtb + (size_t)rowd * SEQ + j0 + jj * 8);
    }
}
#endif

__global__ __launch_bounds__(256, 2) void tc_attention_kernel(
    const float* __restrict__ q, const float* __restrict__ k,
    const __nv_bfloat16* __restrict__ vt, float* __restrict__ ctx)
{
#if HAS_TCGEN05
    extern __shared__ __align__(1024) char smem[];
    const uint32_t sbase = smem_u32(smem);
    const uint32_t mbar  = sbase + ASM_CTRL + 8;
    const int tid = threadIdx.x;
    const int wid = tid >> 5;
    const int lid = tid & 31;

    const int bh = blockIdx.y;
    const int b  = bh / NH;
    const int h  = bh % NH;
    const int q0 = blockIdx.x * 128;

    const float* qb  = q  + (size_t)(b * SEQ + q0) * DM + h * DK;
    const float* kb  = k  + (size_t)b * SEQ * DM + h * DK;
    const __nv_bfloat16* vtb = vt + (size_t)bh * DK * SEQ;

    if (wid == 0) {
        asm volatile("tcgen05.alloc.cta_group::1.sync.aligned.shared::cta.b32 [%0], %1;"
                     :: "r"(sbase + ASM_CTRL), "r"(256u) : "memory");
        asm volatile("tcgen05.relinquish_alloc_permit.cta_group::1.sync.aligned;");
    }
    if (tid == 0) mbar_init(mbar, 1);
    __syncthreads();
    uint32_t tmem_base;
    asm volatile("ld.shared.b32 %0, [%1];" : "=r"(tmem_base) : "r"(sbase + ASM_CTRL));
    const uint32_t tS = tmem_base;
    const uint32_t tO = tmem_base + 128;

    // ---- Q load ----
#pragma unroll
    for (int t = 0; t < 8; ++t) {
        int i   = tid + t * 256;
        int row = i >> 4;
        int d0  = (i & 15) * 4;
        cp16(sbase + ASM_Q + ((uint32_t)(d0 >> 5)) * 16384u
             + SW128((uint32_t)(row * 128 + (d0 & 31) * 4)),
             qb + (size_t)row * DM + d0);
    }
    // K(0) into slot 0, V(0)
    attn_load_k(kb, sbase + ASM_KP, 0, tid);
    attn_load_v(vtb, sbase, 0, tid);
    cp_commit();

    const int sub  = wid & 3;
    const int half = wid >> 2;
    const int r    = sub * 32 + lid;

    float lsum = 0.f;
    uint32_t cnt = 0;

    const uint64_t dQ = make_desc(sbase + ASM_Q);
    const int NITER = SEQ / 128;   // 16

    for (int j = 0; j < NITER; ++j) {
        const uint32_t slot  = sbase + ASM_KP + (uint32_t)(j & 1) * 32768u;
        const uint32_t slotP = sbase + ASM_KP + (uint32_t)((j - 1) & 1) * 32768u;

        // (1) all pending loads (K(j), V(j-1)) landed
        cp_wait0();
        asm volatile("fence.proxy.async.shared::cta;" ::: "memory");
        __syncthreads();

        // (2) fused commit: MMA2(j-1) bf16 + MMA1(j) tf32
        if (tid == 0) {
            asm volatile("tcgen05.fence::after_thread_sync;" ::: "memory");
            if (j > 0) {
                uint64_t dP = make_desc(slotP);
                uint64_t dV = make_desc(sbase + ASM_V);
#pragma unroll
                for (int s = 0; s < 8; ++s) {   // K=16 bf16 per step
                    uint64_t offA = (uint64_t)((s >> 2) * 1024 + (s & 3) * 2);
                    uint64_t offB = (uint64_t)((s >> 2) * 512  + (s & 3) * 2);
                    mma_bf16_ss(tO, dP + offA, dV + offB, IDESC_BF16(128,64),
                                (j > 1 || s > 0) ? 1u : 0u);
                }
            }
            uint64_t dK = make_desc(slot);
#pragma unroll
            for (int s = 0; s < 8; ++s) {
                uint64_t off = (uint64_t)((s >> 2) * 1024 + (s & 3) * 2);
                mma_tf32_ss(tS, dQ + off, dK + off, IDESC_TF32(128,128), s > 0 ? 1u : 0u);
            }
            asm volatile(
                "tcgen05.commit.cta_group::1.mbarrier::arrive::one.shared::cluster.b64 [%0];"
                :: "r"(mbar) : "memory");
        }
        mbar_wait(mbar, cnt & 1); ++cnt;
        asm volatile("tcgen05.fence::after_thread_sync;" ::: "memory");

        // (3) prefetch K(j+1) into other slot (freed by MMA2(j-1)); V(j) (freed too)
        if (j + 1 < NITER)
            attn_load_k(kb, sbase + ASM_KP + (uint32_t)((j + 1) & 1) * 32768u,
                        (j + 1) * 128, tid);
        if (j + 1 < NITER || j == NITER - 1) { /* V(j) needed by MMA2(j) */ }
        attn_load_v(vtb, sbase, j * 128, tid);
        cp_commit();

        // (4) softmax: P(j) = exp(S/8) -> bf16 into slot (j&1)
#pragma unroll
        for (int g = 0; g < 2; ++g) {
            const int c0 = half * 64 + g * 32;
            uint32_t sreg[32];
            tmem_ld32(sreg, tS + c0);
            asm volatile("tcgen05.wait::ld.sync.aligned;" ::: "memory");
            float p[32];
#pragma unroll
            for (int jj = 0; jj < 32; ++jj) {
                p[jj] = __expf(__uint_as_float(sreg[jj]) * 0.125f);
            }
            // store 16 bf16x2 words: subtile = half, byte = g*64 + w*4
#pragma unroll
            for (int w = 0; w < 16; ++w) {
                __nv_bfloat162 pk = __floats2bfloat162_rn(p[w*2], p[w*2+1]);
                lsum += __bfloat162float(pk.x) + __bfloat162float(pk.y);
                uint32_t addr = slot + (uint32_t)half * 16384u
                              + SW128((uint32_t)(r * 128 + g * 64 + w * 4));
                asm volatile("st.shared.b32 [%0], %1;"
                             :: "r"(addr), "r"(*(uint32_t*)&pk) : "memory");
            }
        }
        __syncthreads();   // all P stores done before next-iter fence+MMA2
    }

    // ---- epilogue MMA2(last): P(15), V(15) ----
    cp_wait0();
    asm volatile("fence.proxy.async.shared::cta;" ::: "memory");
    __syncthreads();
    if (tid == 0) {
        asm volatile("tcgen05.fence::after_thread_sync;" ::: "memory");
        uint64_t dP = make_desc(sbase + ASM_KP + (uint32_t)((NITER - 1) & 1) * 32768u);
        uint64_t dV = make_desc(sbase + ASM_V);
#pragma unroll
        for (int s = 0; s < 8; ++s) {
            uint64_t offA = (uint64_t)((s >> 2) * 1024 + (s & 3) * 2);
            uint64_t offB = (uint64_t)((s >> 2) * 512  + (s & 3) * 2);
            mma_bf16_ss(tO, dP + offA, dV + offB, IDESC_BF16(128,64), 1u);
        }
        asm volatile(
            "tcgen05.commit.cta_group::1.mbarrier::arrive::one.shared::cluster.b64 [%0];"
            :: "r"(mbar) : "memory");
    }
    mbar_wait(mbar, cnt & 1); ++cnt;
    asm volatile("tcgen05.fence::after_thread_sync;" ::: "memory");
    __syncthreads();

    // ---- combine row sums (reuse Q area) ----
    {
        float* l_arr = (float*)(smem + ASM_Q);
        l_arr[half * 128 + r] = lsum;
    }
    __syncthreads();
    float ltot;
    {
        float* l_arr = (float*)(smem + ASM_Q);
        ltot = l_arr[r] + l_arr[128 + r];
    }
    const float inv = 1.f / ltot;

    // ---- O epilogue ----
    {
        const int c0 = half * 32;
        uint32_t oreg[32];
        tmem_ld32(oreg, tO + c0);
        asm volatile("tcgen05.wait::ld.sync.aligned;" ::: "memory");
        float* orow = ctx + (size_t)(b * SEQ + q0 + r) * DM + h * DK + c0;
#pragma unroll
        for (int j4 = 0; j4 < 8; ++j4) {
            float4 o;
            o.x = __uint_as_float(oreg[j4*4+0]) * inv;
            o.y = __uint_as_float(oreg[j4*4+1]) * inv;
            o.z = __uint_as_float(oreg[j4*4+2]) * inv;
            o.w = __uint_as_float(oreg[j4*4+3]) * inv;
            *(float4*)(orow + j4 * 4) = o;
        }
    }
    asm volatile("tcgen05.fence::before_thread_sync;" ::: "memory");
    __syncthreads();
    if (wid == 0) {
        asm volatile("tcgen05.dealloc.cta_group::1.sync.aligned.b32 %0, %1;"
                     :: "r"(tmem_base), "r"(256u));
    }
#endif
}

// ======================= fused weight transpose (ALL 6 in one launch) ========
__global__ __launch_bounds__(256) void transpose_all_kernel(
    const float* __restrict__ Wq, const float* __restrict__ Wk,
    const float* __restrict__ Wv, const float* __restrict__ Wo,
    const float* __restrict__ W1, const float* __restrict__ W2,
    float* __restrict__ Wqkv, float* __restrict__ Wot,
    float* __restrict__ W1t,  float* __restrict__ W2t)
{
    __shared__ float t[32][33];
    const int bid = blockIdx.x;
    const float* in; float* out; int R, C, idx;

    if (bid < 4096) {
        R = DM; C = DM; idx = bid & 1023;
        const int j = bid >> 10;
        in  = (j == 0) ? Wq : (j == 1) ? Wk : (j == 2) ? Wv : Wo;
        out = (j == 3) ? Wot : Wqkv + (size_t)j * DM * DM;
    } else if (bid < 8192) {
        R = DM; C = DFF; idx = bid - 4096;
        in = W1; out = W1t;
    } else {
        R = DFF; C = DM; idx = bid - 8192;
        in = W2; out = W2t;
    }
    const int Ct = C >> 5;
    const int c0 = (idx % Ct) * 32;
    const int r0 = (idx / Ct) * 32;
    const int x = threadIdx.x & 31;
    const int y = threadIdx.x >> 5;
#pragma unroll
    for (int i = y; i < 32; i += 8)
        t[i][x] = in[(size_t)(r0 + i) * C + c0 + x];
    __syncthreads();
#pragma unroll
    for (int i = y; i < 32; i += 8)
        out[(size_t)(c0 + i) * R + r0 + x] = __uint_as_float(f2tf32(t[x][i]));
}

// ======================= fused residual + LayerNorm ==========================
__global__ __launch_bounds__(256) void ln_residual_kernel(
    const float* __restrict__ X, const float* __restrict__ Y,
    const float* __restrict__ g, const float* __restrict__ be,
    float* __restrict__ out)
{
    __shared__ float buf[DM];
    __shared__ float red1[256], red2[256];

    const int row = blockIdx.x;
    const int tid = threadIdx.x;
    const size_t base = (size_t)row * DM;

    float s = 0.f, s2 = 0.f;
#pragma unroll
    for (int c = tid; c < DM; c += 256) {
        float vv = X[base + c] + Y[base + c];
        buf[c] = vv;
        s  += vv;
        s2 += vv * vv;
    }
    red1[tid] = s; red2[tid] = s2;
    __syncthreads();
    for (int off = 128; off > 0; off >>= 1) {
        if (tid < off) {
            red1[tid] += red1[tid + off];
            red2[tid] += red2[tid + off];
        }
        __syncthreads();
    }
    const float mu  = red1[0] * (1.f / DM);
    const float var = red2[0] * (1.f / DM) - mu * mu;
    const float rs  = rsqrtf(var + 1e-5f);

#pragma unroll
    for (int c = tid; c < DM; c += 256)
        out[base + c] = (buf[c] - mu) * rs * g[c] + be[c];
}

// ======================= launch ==============================================
extern "C" void kernel_launch(void* const* d_in, const int* in_sizes, int n_in,
                              void* d_out, int out_size)
{
    const float* x  = (const float*)d_in[0];
    const float* Wq = (const float*)d_in[1];  const float* bq = (const float*)d_in[2];
    const float* Wk = (const float*)d_in[3];  const float* bk = (const float*)d_in[4];
    const float* Wv = (const float*)d_in[5];  const float* bv = (const float*)d_in[6];
    const float* Wo = (const float*)d_in[7];  const float* bo = (const float*)d_in[8];
    const float* W1 = (const float*)d_in[9];  const float* b1 = (const float*)d_in[10];
    const float* W2 = (const float*)d_in[11]; const float* b2 = (const float*)d_in[12];
    const float* g1 = (const float*)d_in[13]; const float* be1 = (const float*)d_in[14];
    const float* g2 = (const float*)d_in[15]; const float* be2 = (const float*)d_in[16];

    float *q, *k, *ctx, *att, *h, *ff1, *ff2;
    __nv_bfloat16* vt;
    float *Wqkv, *Wot, *W1t, *W2t;
    cudaGetSymbolAddress((void**)&q,    g_q);
    cudaGetSymbolAddress((void**)&k,    g_k);
    cudaGetSymbolAddress((void**)&vt,   g_vt);
    cudaGetSymbolAddress((void**)&ctx,  g_ctx);
    cudaGetSymbolAddress((void**)&att,  g_att);
    cudaGetSymbolAddress((void**)&h,    g_h);
    cudaGetSymbolAddress((void**)&ff1,  g_ff1);
    cudaGetSymbolAddress((void**)&ff2,  g_ff2);
    cudaGetSymbolAddress((void**)&Wqkv, g_Wqkv);
    cudaGetSymbolAddress((void**)&Wot,  g_Wot);
    cudaGetSymbolAddress((void**)&W1t,  g_W1t);
    cudaGetSymbolAddress((void**)&W2t,  g_W2t);

    static int smem_set = 0;
    if (!smem_set) {
        cudaFuncSetAttribute(tc_attention_kernel,
                             cudaFuncAttributeMaxDynamicSharedMemorySize, ASM_SIZE);
        cudaFuncSetAttribute(tc_gemm_kernel,
                             cudaFuncAttributeMaxDynamicSharedMemorySize, GSM_SIZE);
        smem_set = 1;
    }

    // ---- all 6 weight transposes (tf32-rounded) in ONE launch ----
    transpose_all_kernel<<<12288, 256>>>(Wq, Wk, Wv, Wo, W1, W2,
                                         Wqkv, Wot, W1t, W2t);

    const dim3 gQKV (3*DM / 128, MTOT / 128);   // (24, 32)
    const dim3 gProj(DM / 128,   MTOT / 128);   // (8, 32)
    const dim3 gFF1 (DFF / 128,  MTOT / 128);   // (32, 32)

    // fused QKV projection (V written transposed as bf16)
    tc_gemm_kernel<<<gQKV, 256, GSM_SIZE>>>(x, Wqkv, bq, bk, bv, q, k, vt, MTOT, 3*DM, DM, 2);

    // attention (fused-commit, bf16 P/V)
    tc_attention_kernel<<<dim3(SEQ / 128, BATCH * NH), 256, ASM_SIZE>>>(q, k, vt, ctx);

    // output projection
    tc_gemm_kernel<<<gProj, 256, GSM_SIZE>>>(ctx, Wot, bo, 0, 0, att, 0, 0, MTOT, DM, DM, 0);

    // residual + LN1 -> h
    ln_residual_kernel<<<MTOT, 256>>>(x, att, g1, be1, h);

    // FFN
    tc_gemm_kernel<<<gFF1, 256, GSM_SIZE>>>(h, W1t, b1, 0, 0, ff1, 0, 0, MTOT, DFF, DM, 1);
    tc_gemm_kernel<<<gProj, 256, GSM_SIZE>>>(ff1, W2t, b2, 0, 0, ff2, 0, 0, MTOT, DM, DFF, 0);

    // residual + LN2 -> output
    ln_residual_kernel<<<MTOT, 256>>>(h, ff2, g2, be2, (float*)d_out);
}